// round 1
// baseline (speedup 1.0000x reference)
#include <cuda_runtime.h>
#include <math.h>

#define DD 128
#define MT 64
#define NTHREADS 256

// ---------------- f32x2 packed-FMA helpers (SASS FFMA2; 2x fp32 rate) ------
__device__ __forceinline__ unsigned long long dup2(float w) {
    unsigned long long r;
    asm("mov.b64 %0, {%1, %1};" : "=l"(r) : "f"(w));
    return r;
}
__device__ __forceinline__ void fma2(unsigned long long &d, unsigned long long a, unsigned long long b) {
    asm("fma.rn.f32x2 %0, %1, %2, %0;" : "+l"(d) : "l"(a), "l"(b));
}
__device__ __forceinline__ float2 u2f(unsigned long long v) {
    float2 r;
    asm("mov.b64 {%0, %1}, %2;" : "=f"(r.x), "=f"(r.y) : "l"(v));
    return r;
}

// ---------------- one layer: Y[n][m] = act(X @ W + b) --------------------
// X: [K][64] feature-major in smem. W: [K][128] row-major in global.
// Output Y: [128][64] feature-major in smem.
// flags: 1 = relu, 2 = multiply by sVH[n][m] after relu.
__device__ __noinline__ void gemm_tile(
    const float* __restrict__ Xf, float* __restrict__ Yf,
    const float* __restrict__ gW, const float* __restrict__ gB,
    float* sW, float* sB, const float* sVH,
    int K, int flags)
{
    const int tid = threadIdx.x;

    // stage weights + bias into smem
    {
        const float4* gW4 = (const float4*)gW;
        float4* sW4 = (float4*)sW;
        int total4 = K * (DD / 4);
        for (int i = tid; i < total4; i += NTHREADS) sW4[i] = gW4[i];
        if (tid < DD) sB[tid] = gB[tid];
    }
    __syncthreads();

    unsigned long long acc[4][4];
#pragma unroll
    for (int j = 0; j < 4; j++)
#pragma unroll
        for (int p = 0; p < 4; p++) acc[j][p] = 0ULL;

    const int mg = tid & 7;         // m-group: pixels mg*8 .. mg*8+7
    const int ng = tid >> 3;        // n-group: features ng*4 .. ng*4+3
    const char* Xb = (const char*)Xf + mg * 32;
    const char* Wb = (const char*)sW + ng * 16;

#pragma unroll 4
    for (int k = 0; k < K; ++k) {
        ulonglong2 a0 = *(const ulonglong2*)(Xb + (size_t)k * 256);
        ulonglong2 a1 = *(const ulonglong2*)(Xb + (size_t)k * 256 + 16);
        float4 w = *(const float4*)(Wb + (size_t)k * 512);
        unsigned long long w0 = dup2(w.x), w1 = dup2(w.y), w2 = dup2(w.z), w3 = dup2(w.w);
        fma2(acc[0][0], a0.x, w0); fma2(acc[0][1], a0.y, w0);
        fma2(acc[0][2], a1.x, w0); fma2(acc[0][3], a1.y, w0);
        fma2(acc[1][0], a0.x, w1); fma2(acc[1][1], a0.y, w1);
        fma2(acc[1][2], a1.x, w1); fma2(acc[1][3], a1.y, w1);
        fma2(acc[2][0], a0.x, w2); fma2(acc[2][1], a0.y, w2);
        fma2(acc[2][2], a1.x, w2); fma2(acc[2][3], a1.y, w2);
        fma2(acc[3][0], a0.x, w3); fma2(acc[3][1], a0.y, w3);
        fma2(acc[3][2], a1.x, w3); fma2(acc[3][3], a1.y, w3);
    }

    const int m0 = mg * 8, n0 = ng * 4;
#pragma unroll
    for (int j = 0; j < 4; j++) {
        int n = n0 + j;
        float b = sB[n];
        float v[8];
#pragma unroll
        for (int p = 0; p < 4; p++) {
            float2 f = u2f(acc[j][p]);
            v[2 * p]     = f.x + b;
            v[2 * p + 1] = f.y + b;
        }
        if (flags & 1) {
#pragma unroll
            for (int t = 0; t < 8; t++) v[t] = fmaxf(v[t], 0.0f);
        }
        if (flags & 2) {
#pragma unroll
            for (int t = 0; t < 8; t++) v[t] *= sVH[n * MT + m0 + t];
        }
        float4 o0 = make_float4(v[0], v[1], v[2], v[3]);
        float4 o1 = make_float4(v[4], v[5], v[6], v[7]);
        *(float4*)&Yf[n * MT + m0]     = o0;
        *(float4*)&Yf[n * MT + m0 + 4] = o1;
    }
    __syncthreads();
}

// ---------------- fused kernel: 64 pixels per CTA -------------------------
__global__ void __launch_bounds__(NTHREADS, 1) rc_fused_kernel(
    const int* __restrict__ vidx, const float* __restrict__ bary,
    const float* __restrict__ vdir, const float* __restrict__ emb,
    const float* __restrict__ vde_W, const float* __restrict__ vde_b,
    const float* __restrict__ vh_W, const float* __restrict__ vh_b,
    const float* __restrict__ hid_W, const float* __restrict__ hid_b,
    const float* __restrict__ hW0, const float* __restrict__ hb0,
    const float* __restrict__ hW1, const float* __restrict__ hb1,
    const float* __restrict__ hW2, const float* __restrict__ hb2,
    float* __restrict__ out, int n_pix)
{
    extern __shared__ float sm[];
    float* sX   = sm;                 // [128][64]
    float* sY   = sX + 8192;          // [128][64]
    float* sVH  = sY + 8192;          // [128][64]
    float* sW   = sVH + 8192;         // [128][128]
    float* sB   = sW + 16384;         // [128]
    float* sPE  = sB + 128;           // [18][64]
    float* sScl = sPE + 1152;         // [3][64]
    int*   sIdx = (int*)(sScl + 192); // [3][64]

    const int tid = threadIdx.x;
    const int base = blockIdx.x * MT;

    // ---- phase 1: vertex renorm scales (warps 0-5) + PE (warps 6-7) ----
    if (tid < 192) {
        int m = tid & 63, j = tid >> 6;
        int pix = base + m; if (pix >= n_pix) pix = n_pix - 1;
        int idx = vidx[pix * 3 + j] + 1;
        float bw = bary[pix * 3 + j];
        const float4* row = (const float4*)(emb + (size_t)idx * DD);
        float ss = 0.f;
#pragma unroll
        for (int i = 0; i < 32; i++) {
            float4 e = row[i];
            ss += e.x * e.x + e.y * e.y + e.z * e.z + e.w * e.w;
        }
        float nrm = sqrtf(ss);
        float sc = (nrm > 1.0f) ? (1.0f / (nrm + 1e-7f)) : 1.0f;
        sScl[j * 64 + m] = bw * sc;
        sIdx[j * 64 + m] = idx;
    } else {
        int m = tid - 192;
        int pix = base + m; if (pix >= n_pix) pix = n_pix - 1;
        float vd[3];
        vd[0] = vdir[pix * 3 + 0];
        vd[1] = vdir[pix * 3 + 1];
        vd[2] = vdir[pix * 3 + 2];
        float sg[3];
#pragma unroll
        for (int j = 0; j < 3; j++)
            sg[j] = 6.283185307179586f / powf(0.9f, (float)(2 * j) / 6.0f);
#pragma unroll
        for (int i = 0; i < 3; i++) {
#pragma unroll
            for (int j = 0; j < 3; j++) {
                float p = vd[i] * sg[j];
                sPE[(i * 6 + j)     * 64 + m] = sinf(p);
                sPE[(i * 6 + j + 3) * 64 + m] = cosf(p);
            }
        }
    }
    __syncthreads();

    // ---- phase 2: barycentric-weighted embedding sum -> sX (feature-major)
    {
        int m = tid & 63, dc = tid >> 6;
        int d0 = dc * 32;
        float4 a[8];
#pragma unroll
        for (int i = 0; i < 8; i++) a[i] = make_float4(0.f, 0.f, 0.f, 0.f);
#pragma unroll
        for (int j = 0; j < 3; j++) {
            int idx = sIdx[j * 64 + m];
            float s = sScl[j * 64 + m];
            const float4* row = (const float4*)(emb + (size_t)idx * DD + d0);
#pragma unroll
            for (int i = 0; i < 8; i++) {
                float4 e = row[i];
                a[i].x += s * e.x; a[i].y += s * e.y;
                a[i].z += s * e.z; a[i].w += s * e.w;
            }
        }
#pragma unroll
        for (int i = 0; i < 8; i++) {
            int d = d0 + i * 4;
            sX[(d + 0) * 64 + m] = a[i].x;
            sX[(d + 1) * 64 + m] = a[i].y;
            sX[(d + 2) * 64 + m] = a[i].z;
            sX[(d + 3) * 64 + m] = a[i].w;
        }
    }
    __syncthreads();

    // ---- view-dir branch: vh ends in sVH ----
    gemm_tile(sPE, sY,  vde_W,            vde_b,        sW, sB, sVH, 18,  0);
    gemm_tile(sY,  sVH, vh_W + 0 * 16384, vh_b + 0,     sW, sB, sVH, 128, 1);
    gemm_tile(sVH, sY,  vh_W + 1 * 16384, vh_b + 128,   sW, sB, sVH, 128, 1);
    gemm_tile(sY,  sVH, vh_W + 2 * 16384, vh_b + 256,   sW, sB, sVH, 128, 1);
    // ---- hidden chain (vh modulation after block 0) ----
    gemm_tile(sX,  sY,  hid_W + 0 * 16384, hid_b + 0,   sW, sB, sVH, 128, 1);
    gemm_tile(sY,  sX,  hid_W + 1 * 16384, hid_b + 128, sW, sB, sVH, 128, 1);
    gemm_tile(sX,  sY,  hid_W + 2 * 16384, hid_b + 256, sW, sB, sVH, 128, 3);
    gemm_tile(sY,  sX,  hid_W + 3 * 16384, hid_b + 384, sW, sB, sVH, 128, 1);
    gemm_tile(sX,  sY,  hid_W + 4 * 16384, hid_b + 512, sW, sB, sVH, 128, 1);
    gemm_tile(sY,  sX,  hid_W + 5 * 16384, hid_b + 640, sW, sB, sVH, 128, 1);
    // ---- head ----
    gemm_tile(sX,  sY,  hW0, hb0, sW, sB, sVH, 128, 1);
    gemm_tile(sY,  sX,  hW1, hb1, sW, sB, sVH, 128, 1);

    // head2: 128 -> 4, no relu; write straight to gmem
    for (int i = tid; i < 512; i += NTHREADS) sW[i] = hW2[i];
    __syncthreads();
    {
        int m = tid >> 2, c = tid & 3;
        float acc = hb2[c];
#pragma unroll 8
        for (int k = 0; k < 128; k++)
            acc += sX[k * 64 + m] * sW[k * 4 + c];
        int pix = base + m;
        if (pix < n_pix) out[pix * 4 + c] = acc;
    }
}

// ---------------- launch --------------------------------------------------
extern "C" void kernel_launch(void* const* d_in, const int* in_sizes, int n_in,
                              void* d_out, int out_size)
{
    const int*   vidx  = (const int*)  d_in[0];
    const float* bary  = (const float*)d_in[1];
    const float* vdir  = (const float*)d_in[2];
    const float* emb   = (const float*)d_in[3];
    const float* vde_W = (const float*)d_in[4];
    const float* vde_b = (const float*)d_in[5];
    const float* vh_W  = (const float*)d_in[6];
    const float* vh_b  = (const float*)d_in[7];
    const float* hid_W = (const float*)d_in[8];
    const float* hid_b = (const float*)d_in[9];
    const float* hW0   = (const float*)d_in[10];
    const float* hb0   = (const float*)d_in[11];
    const float* hW1   = (const float*)d_in[12];
    const float* hb1   = (const float*)d_in[13];
    const float* hW2   = (const float*)d_in[14];
    const float* hb2   = (const float*)d_in[15];
    float* out = (float*)d_out;

    int n_pix = in_sizes[0] / 3;
    int grid = (n_pix + MT - 1) / MT;

    const int SMEM_BYTES = (8192 * 3 + 16384 + 128 + 1152 + 192 + 192) * 4; // 170496
    cudaFuncSetAttribute(rc_fused_kernel,
                         cudaFuncAttributeMaxDynamicSharedMemorySize, SMEM_BYTES);

    rc_fused_kernel<<<grid, NTHREADS, SMEM_BYTES>>>(
        vidx, bary, vdir, emb, vde_W, vde_b, vh_W, vh_b, hid_W, hid_b,
        hW0, hb0, hW1, hb1, hW2, hb2, out, n_pix);
}

// round 2
// speedup vs baseline: 1.5177x; 1.5177x over previous
#include <cuda_runtime.h>
#include <math.h>

#define DD 128
#define MT 128          // pixels per CTA
#define NTHREADS 256

typedef unsigned long long ull;

// ---------------- f32x2 packed-FMA helpers (SASS FFMA2; 2x fp32 rate) ------
__device__ __forceinline__ ull dup2(float w) {
    ull r;
    asm("mov.b64 %0, {%1, %1};" : "=l"(r) : "f"(w));
    return r;
}
__device__ __forceinline__ void fma2(ull &d, ull a, ull b) {
    asm("fma.rn.f32x2 %0, %1, %2, %0;" : "+l"(d) : "l"(a), "l"(b));
}
__device__ __forceinline__ float2 u2f(ull v) {
    float2 r;
    asm("mov.b64 {%0, %1}, %2;" : "=f"(r.x), "=f"(r.y) : "l"(v));
    return r;
}

// ---------------- one layer: Y[n][m] = act(X @ W + b) ----------------------
// X: [K][128] feature-major in smem. W: [K][128] row-major, read from global.
// Y: [128][128] feature-major in smem.
// flags: 1 = relu, 2 = multiply by sVH[n][m] after relu.
// Exactly ONE __syncthreads at the end (safe: layer L reads only the buffer
// layer L-1 wrote, and writes a buffer nobody reads during layer L).
__device__ __forceinline__ void gemm_tile(
    const float* __restrict__ Xf, float* __restrict__ Yf,
    const float* __restrict__ gW, const float* __restrict__ gB,
    const float* __restrict__ sVH, int K, int flags)
{
    const int tid = threadIdx.x;
    const int mg = tid & 15;        // pixels mg*8 .. mg*8+7
    const int ng = tid >> 4;        // features ng*8 .. ng*8+7

    ull acc[8][4];
#pragma unroll
    for (int j = 0; j < 8; j++)
#pragma unroll
        for (int p = 0; p < 4; p++) acc[j][p] = 0ULL;

    const char* Xb = (const char*)Xf + mg * 32;        // 8 floats of m
    const float4* Wp = ((const float4*)gW) + ng * 2;   // 8 floats of n

#pragma unroll 8
    for (int k = 0; k < K; ++k) {
        ulonglong2 a0 = *(const ulonglong2*)(Xb + (size_t)k * 512);
        ulonglong2 a1 = *(const ulonglong2*)(Xb + (size_t)k * 512 + 16);
        float4 wA = Wp[(size_t)k * 32];
        float4 wB = Wp[(size_t)k * 32 + 1];
        ull w0 = dup2(wA.x), w1 = dup2(wA.y), w2 = dup2(wA.z), w3 = dup2(wA.w);
        ull w4 = dup2(wB.x), w5 = dup2(wB.y), w6 = dup2(wB.z), w7 = dup2(wB.w);
        fma2(acc[0][0], a0.x, w0); fma2(acc[0][1], a0.y, w0);
        fma2(acc[0][2], a1.x, w0); fma2(acc[0][3], a1.y, w0);
        fma2(acc[1][0], a0.x, w1); fma2(acc[1][1], a0.y, w1);
        fma2(acc[1][2], a1.x, w1); fma2(acc[1][3], a1.y, w1);
        fma2(acc[2][0], a0.x, w2); fma2(acc[2][1], a0.y, w2);
        fma2(acc[2][2], a1.x, w2); fma2(acc[2][3], a1.y, w2);
        fma2(acc[3][0], a0.x, w3); fma2(acc[3][1], a0.y, w3);
        fma2(acc[3][2], a1.x, w3); fma2(acc[3][3], a1.y, w3);
        fma2(acc[4][0], a0.x, w4); fma2(acc[4][1], a0.y, w4);
        fma2(acc[4][2], a1.x, w4); fma2(acc[4][3], a1.y, w4);
        fma2(acc[5][0], a0.x, w5); fma2(acc[5][1], a0.y, w5);
        fma2(acc[5][2], a1.x, w5); fma2(acc[5][3], a1.y, w5);
        fma2(acc[6][0], a0.x, w6); fma2(acc[6][1], a0.y, w6);
        fma2(acc[6][2], a1.x, w6); fma2(acc[6][3], a1.y, w6);
        fma2(acc[7][0], a0.x, w7); fma2(acc[7][1], a0.y, w7);
        fma2(acc[7][2], a1.x, w7); fma2(acc[7][3], a1.y, w7);
    }

    const int m0 = mg * 8, n0 = ng * 8;
#pragma unroll
    for (int j = 0; j < 8; j++) {
        const int n = n0 + j;
        const float b = gB[n];
        float v[8];
#pragma unroll
        for (int p = 0; p < 4; p++) {
            float2 f = u2f(acc[j][p]);
            v[2 * p]     = f.x + b;
            v[2 * p + 1] = f.y + b;
        }
        if (flags & 1) {
#pragma unroll
            for (int t = 0; t < 8; t++) v[t] = fmaxf(v[t], 0.0f);
        }
        if (flags & 2) {
#pragma unroll
            for (int t = 0; t < 8; t++) v[t] *= sVH[n * MT + m0 + t];
        }
        *(float4*)&Yf[n * MT + m0]     = make_float4(v[0], v[1], v[2], v[3]);
        *(float4*)&Yf[n * MT + m0 + 4] = make_float4(v[4], v[5], v[6], v[7]);
    }
    __syncthreads();
}

// ---------------- fused kernel: 128 pixels per CTA -------------------------
__global__ void __launch_bounds__(NTHREADS, 1) rc_fused_kernel(
    const int* __restrict__ vidx, const float* __restrict__ bary,
    const float* __restrict__ vdir, const float* __restrict__ emb,
    const float* __restrict__ vde_W, const float* __restrict__ vde_b,
    const float* __restrict__ vh_W, const float* __restrict__ vh_b,
    const float* __restrict__ hid_W, const float* __restrict__ hid_b,
    const float* __restrict__ hW0, const float* __restrict__ hb0,
    const float* __restrict__ hW1, const float* __restrict__ hb1,
    const float* __restrict__ hW2, const float* __restrict__ hb2,
    float* __restrict__ out, int n_pix)
{
    extern __shared__ float sm[];
    float* sX   = sm;                   // [128][128]
    float* sY   = sX  + DD * MT;        // [128][128]
    float* sVH  = sY  + DD * MT;        // [128][128]
    float* sPE  = sVH + DD * MT;        // [18][128]
    float* sScl = sPE + 18 * MT;        // [3][128]
    int*   sIdx = (int*)(sScl + 3 * MT);// [3][128]
    float* sW2  = (float*)(sIdx + 3 * MT); // [512]

    const int tid  = threadIdx.x;
    const int base = blockIdx.x * MT;

    // ---- phase 1a: per-vertex renorm scales (384 jobs) ----
    for (int job = tid; job < 3 * MT; job += NTHREADS) {
        int m = job & (MT - 1), j = job >> 7;
        int pix = base + m; if (pix >= n_pix) pix = n_pix - 1;
        int idx = vidx[pix * 3 + j] + 1;
        float bw = bary[pix * 3 + j];
        const float4* row = (const float4*)(emb + (size_t)idx * DD);
        float ss = 0.f;
#pragma unroll
        for (int i = 0; i < 32; i++) {
            float4 e = row[i];
            ss += e.x * e.x + e.y * e.y + e.z * e.z + e.w * e.w;
        }
        float nrm = sqrtf(ss);
        float sc = (nrm > 1.0f) ? (1.0f / (nrm + 1e-7f)) : 1.0f;
        sScl[j * MT + m] = bw * sc;
        sIdx[j * MT + m] = idx;
    }

    // ---- phase 1b: sin/cos positional encoding (128 jobs) ----
    for (int m = tid; m < MT; m += NTHREADS) {
        int pix = base + m; if (pix >= n_pix) pix = n_pix - 1;
        float vd[3];
        vd[0] = vdir[pix * 3 + 0];
        vd[1] = vdir[pix * 3 + 1];
        vd[2] = vdir[pix * 3 + 2];
        float sg[3];
#pragma unroll
        for (int j = 0; j < 3; j++)
            sg[j] = 6.283185307179586f / powf(0.9f, (float)(2 * j) / 6.0f);
#pragma unroll
        for (int i = 0; i < 3; i++)
#pragma unroll
            for (int j = 0; j < 3; j++) {
                float p = vd[i] * sg[j];
                sPE[(i * 6 + j)     * MT + m] = sinf(p);
                sPE[(i * 6 + j + 3) * MT + m] = cosf(p);
            }
    }
    __syncthreads();

    // ---- phase 2: barycentric-weighted embedding sum -> sX (feature-major)
    {
        int m = tid & (MT - 1), dc = tid >> 7;   // dc in {0,1}, 64 d each
        int d0 = dc * 64;
        float4 a[16];
#pragma unroll
        for (int i = 0; i < 16; i++) a[i] = make_float4(0.f, 0.f, 0.f, 0.f);
#pragma unroll
        for (int j = 0; j < 3; j++) {
            int idx  = sIdx[j * MT + m];
            float s  = sScl[j * MT + m];
            const float4* row = (const float4*)(emb + (size_t)idx * DD + d0);
#pragma unroll
            for (int i = 0; i < 16; i++) {
                float4 e = row[i];
                a[i].x += s * e.x; a[i].y += s * e.y;
                a[i].z += s * e.z; a[i].w += s * e.w;
            }
        }
#pragma unroll
        for (int i = 0; i < 16; i++) {
            int d = d0 + i * 4;
            sX[(d + 0) * MT + m] = a[i].x;
            sX[(d + 1) * MT + m] = a[i].y;
            sX[(d + 2) * MT + m] = a[i].z;
            sX[(d + 3) * MT + m] = a[i].w;
        }
    }
    __syncthreads();

    // ---- view-dir branch: vh ends in sVH ----
    gemm_tile(sPE, sY,  vde_W,             vde_b,       sVH, 18,  0);
    gemm_tile(sY,  sVH, vh_W + 0 * 16384,  vh_b + 0,    sVH, DD, 1);
    gemm_tile(sVH, sY,  vh_W + 1 * 16384,  vh_b + 128,  sVH, DD, 1);
    gemm_tile(sY,  sVH, vh_W + 2 * 16384,  vh_b + 256,  sVH, DD, 1);
    // ---- hidden chain (vh modulation after block 0) ----
    gemm_tile(sX,  sY,  hid_W + 0 * 16384, hid_b + 0,   sVH, DD, 1);
    gemm_tile(sY,  sX,  hid_W + 1 * 16384, hid_b + 128, sVH, DD, 1);
    gemm_tile(sX,  sY,  hid_W + 2 * 16384, hid_b + 256, sVH, DD, 3);
    gemm_tile(sY,  sX,  hid_W + 3 * 16384, hid_b + 384, sVH, DD, 1);
    gemm_tile(sX,  sY,  hid_W + 4 * 16384, hid_b + 512, sVH, DD, 1);
    gemm_tile(sY,  sX,  hid_W + 5 * 16384, hid_b + 640, sVH, DD, 1);
    // ---- head ----
    gemm_tile(sX,  sY,  hW0, hb0, sVH, DD, 1);
    gemm_tile(sY,  sX,  hW1, hb1, sVH, DD, 1);

    // head2: 128 -> 4, no relu; write straight to gmem
    for (int i = tid; i < 512; i += NTHREADS) sW2[i] = hW2[i];
    __syncthreads();
    for (int o = tid; o < MT * 4; o += NTHREADS) {
        int m = o >> 2, c = o & 3;
        float acc = hb2[c];
#pragma unroll 8
        for (int k = 0; k < DD; k++)
            acc += sX[k * MT + m] * sW2[k * 4 + c];
        int pix = base + m;
        if (pix < n_pix) out[pix * 4 + c] = acc;
    }
}

// ---------------- launch --------------------------------------------------
extern "C" void kernel_launch(void* const* d_in, const int* in_sizes, int n_in,
                              void* d_out, int out_size)
{
    const int*   vidx  = (const int*)  d_in[0];
    const float* bary  = (const float*)d_in[1];
    const float* vdir  = (const float*)d_in[2];
    const float* emb   = (const float*)d_in[3];
    const float* vde_W = (const float*)d_in[4];
    const float* vde_b = (const float*)d_in[5];
    const float* vh_W  = (const float*)d_in[6];
    const float* vh_b  = (const float*)d_in[7];
    const float* hid_W = (const float*)d_in[8];
    const float* hid_b = (const float*)d_in[9];
    const float* hW0   = (const float*)d_in[10];
    const float* hb0   = (const float*)d_in[11];
    const float* hW1   = (const float*)d_in[12];
    const float* hb1   = (const float*)d_in[13];
    const float* hW2   = (const float*)d_in[14];
    const float* hb2   = (const float*)d_in[15];
    float* out = (float*)d_out;

    int n_pix = in_sizes[0] / 3;
    int grid  = (n_pix + MT - 1) / MT;

    // 3*16384 + 18*128 + 3*128 + 3*128 + 512 floats = 52736 floats = 210944 B
    const int SMEM_BYTES = (3 * DD * MT + 18 * MT + 3 * MT + 3 * MT + 512) * 4;
    cudaFuncSetAttribute(rc_fused_kernel,
                         cudaFuncAttributeMaxDynamicSharedMemorySize, SMEM_BYTES);

    rc_fused_kernel<<<grid, NTHREADS, SMEM_BYTES>>>(
        vidx, bary, vdir, emb, vde_W, vde_b, vh_W, vh_b, hid_W, hid_b,
        hW0, hb0, hW1, hb1, hW2, hb2, out, n_pix);
}

// round 4
// speedup vs baseline: 1.6568x; 1.0917x over previous
#include <cuda_runtime.h>
#include <math.h>

#define DD 128
#define MT 128          // pixels per CTA
#define NTHREADS 256

typedef unsigned long long ull;

// ---------------- f32x2 packed-FMA helpers (SASS FFMA2; 2x fp32 rate) ------
__device__ __forceinline__ ull dup2(float w) {
    ull r;
    asm("mov.b64 %0, {%1, %1};" : "=l"(r) : "f"(w));
    return r;
}
__device__ __forceinline__ void fma2(ull &d, ull a, ull b) {
    asm("fma.rn.f32x2 %0, %1, %2, %0;" : "+l"(d) : "l"(a), "l"(b));
}
__device__ __forceinline__ float2 u2f(ull v) {
    float2 r;
    asm("mov.b64 {%0, %1}, %2;" : "=f"(r.x), "=f"(r.y) : "l"(v));
    return r;
}

// ---------------- one layer: Y[n][m] = act(X @ W + b) ----------------------
// X: [K][128] feature-major in smem. W: [K][128] row-major, read from global.
// Y: [128][128] feature-major in smem.
// Thread (mg,ng) handles m in {mg*4..mg*4+3} u {64+mg*4..64+mg*4+3},
// n in {ng*8..ng*8+7}. X loads are CONTIGUOUS 16B chunks across mg so each
// warp LDS.128 request spans 256B (2 L1 wavefronts, not 4).
// flags: 1 = relu, 2 = multiply by sVH[n][m] after relu.
__device__ __forceinline__ void gemm_tile(
    const float* __restrict__ Xf, float* __restrict__ Yf,
    const float* __restrict__ gW, const float* __restrict__ gB,
    const float* __restrict__ sVH, int K, int flags)
{
    const int tid = threadIdx.x;
    const int mg = tid & 15;        // m chunks: [mg*4, mg*4+4) and +64
    const int ng = tid >> 4;        // features ng*8 .. ng*8+7

    ull acc[8][4];
#pragma unroll
    for (int j = 0; j < 8; j++)
#pragma unroll
        for (int p = 0; p < 4; p++) acc[j][p] = 0ULL;

    const char* Xb = (const char*)Xf + mg * 16;        // 4 contiguous floats
    const float4* Wp = ((const float4*)gW) + ng * 2;   // 8 floats of n

#pragma unroll 8
    for (int k = 0; k < K; ++k) {
        ulonglong2 a0 = *(const ulonglong2*)(Xb + (size_t)k * 512);        // m: mg*4..+3
        ulonglong2 a1 = *(const ulonglong2*)(Xb + (size_t)k * 512 + 256);  // m: 64+mg*4..+3
        float4 wA = Wp[(size_t)k * 32];
        float4 wB = Wp[(size_t)k * 32 + 1];
        ull w0 = dup2(wA.x), w1 = dup2(wA.y), w2 = dup2(wA.z), w3 = dup2(wA.w);
        ull w4 = dup2(wB.x), w5 = dup2(wB.y), w6 = dup2(wB.z), w7 = dup2(wB.w);
        fma2(acc[0][0], a0.x, w0); fma2(acc[0][1], a0.y, w0);
        fma2(acc[0][2], a1.x, w0); fma2(acc[0][3], a1.y, w0);
        fma2(acc[1][0], a0.x, w1); fma2(acc[1][1], a0.y, w1);
        fma2(acc[1][2], a1.x, w1); fma2(acc[1][3], a1.y, w1);
        fma2(acc[2][0], a0.x, w2); fma2(acc[2][1], a0.y, w2);
        fma2(acc[2][2], a1.x, w2); fma2(acc[2][3], a1.y, w2);
        fma2(acc[3][0], a0.x, w3); fma2(acc[3][1], a0.y, w3);
        fma2(acc[3][2], a1.x, w3); fma2(acc[3][3], a1.y, w3);
        fma2(acc[4][0], a0.x, w4); fma2(acc[4][1], a0.y, w4);
        fma2(acc[4][2], a1.x, w4); fma2(acc[4][3], a1.y, w4);
        fma2(acc[5][0], a0.x, w5); fma2(acc[5][1], a0.y, w5);
        fma2(acc[5][2], a1.x, w5); fma2(acc[5][3], a1.y, w5);
        fma2(acc[6][0], a0.x, w6); fma2(acc[6][1], a0.y, w6);
        fma2(acc[6][2], a1.x, w6); fma2(acc[6][3], a1.y, w6);
        fma2(acc[7][0], a0.x, w7); fma2(acc[7][1], a0.y, w7);
        fma2(acc[7][2], a1.x, w7); fma2(acc[7][3], a1.y, w7);
    }

    const int mA = mg * 4, mB = 64 + mg * 4, n0 = ng * 8;
    float bias[8];
#pragma unroll
    for (int j = 0; j < 8; j++) bias[j] = gB[n0 + j];

#pragma unroll
    for (int j = 0; j < 8; j++) {
        const int n = n0 + j;
        const float b = bias[j];
        float v[8];
#pragma unroll
        for (int p = 0; p < 4; p++) {
            float2 f = u2f(acc[j][p]);
            v[2 * p]     = f.x + b;
            v[2 * p + 1] = f.y + b;
        }
        if (flags & 1) {
#pragma unroll
            for (int t = 0; t < 8; t++) v[t] = fmaxf(v[t], 0.0f);
        }
        if (flags & 2) {
            float4 g0 = *(const float4*)&sVH[n * MT + mA];
            float4 g1 = *(const float4*)&sVH[n * MT + mB];
            v[0] *= g0.x; v[1] *= g0.y; v[2] *= g0.z; v[3] *= g0.w;
            v[4] *= g1.x; v[5] *= g1.y; v[6] *= g1.z; v[7] *= g1.w;
        }
        *(float4*)&Yf[n * MT + mA] = make_float4(v[0], v[1], v[2], v[3]);
        *(float4*)&Yf[n * MT + mB] = make_float4(v[4], v[5], v[6], v[7]);
    }
    __syncthreads();
}

// ---------------- fused kernel: 128 pixels per CTA -------------------------
__global__ void __launch_bounds__(NTHREADS, 1) rc_fused_kernel(
    const int* __restrict__ vidx, const float* __restrict__ bary,
    const float* __restrict__ vdir, const float* __restrict__ emb,
    const float* __restrict__ vde_W, const float* __restrict__ vde_b,
    const float* __restrict__ vh_W, const float* __restrict__ vh_b,
    const float* __restrict__ hid_W, const float* __restrict__ hid_b,
    const float* __restrict__ hW0, const float* __restrict__ hb0,
    const float* __restrict__ hW1, const float* __restrict__ hb1,
    const float* __restrict__ hW2, const float* __restrict__ hb2,
    float* __restrict__ out, int n_pix)
{
    extern __shared__ float sm[];
    float* sX   = sm;                   // [128][128]
    float* sY   = sX  + DD * MT;        // [128][128]
    float* sVH  = sY  + DD * MT;        // [128][128]
    float* sPE  = sVH + DD * MT;        // [18][128]
    float* sScl = sPE + 18 * MT;        // [3][128]
    int*   sIdx = (int*)(sScl + 3 * MT);// [3][128]
    float* sW2  = (float*)(sIdx + 3 * MT); // [512]

    const int tid  = threadIdx.x;
    const int base = blockIdx.x * MT;

    // ---- phase 1a: per-vertex renorm scales (384 jobs) ----
    for (int job = tid; job < 3 * MT; job += NTHREADS) {
        int m = job & (MT - 1), j = job >> 7;
        int pix = base + m; if (pix >= n_pix) pix = n_pix - 1;
        int idx = vidx[pix * 3 + j] + 1;
        float bw = bary[pix * 3 + j];
        const float4* row = (const float4*)(emb + (size_t)idx * DD);
        float ss = 0.f;
#pragma unroll
        for (int i = 0; i < 32; i++) {
            float4 e = row[i];
            ss += e.x * e.x + e.y * e.y + e.z * e.z + e.w * e.w;
        }
        float nrm = sqrtf(ss);
        float sc = (nrm > 1.0f) ? (1.0f / (nrm + 1e-7f)) : 1.0f;
        sScl[j * MT + m] = bw * sc;
        sIdx[j * MT + m] = idx;
    }

    // ---- phase 1b: sin/cos positional encoding (128 jobs) ----
    for (int m = tid; m < MT; m += NTHREADS) {
        int pix = base + m; if (pix >= n_pix) pix = n_pix - 1;
        float vd[3];
        vd[0] = vdir[pix * 3 + 0];
        vd[1] = vdir[pix * 3 + 1];
        vd[2] = vdir[pix * 3 + 2];
        float sg[3];
#pragma unroll
        for (int j = 0; j < 3; j++)
            sg[j] = 6.283185307179586f / powf(0.9f, (float)(2 * j) / 6.0f);
#pragma unroll
        for (int i = 0; i < 3; i++)
#pragma unroll
            for (int j = 0; j < 3; j++) {
                float p = vd[i] * sg[j];
                sPE[(i * 6 + j)     * MT + m] = sinf(p);
                sPE[(i * 6 + j + 3) * MT + m] = cosf(p);
            }
    }
    __syncthreads();

    // ---- phase 2: barycentric-weighted embedding sum -> sX (feature-major)
    {
        int m = tid & (MT - 1), dc = tid >> 7;   // dc in {0,1}, 64 d each
        int d0 = dc * 64;
        float4 a[16];
#pragma unroll
        for (int i = 0; i < 16; i++) a[i] = make_float4(0.f, 0.f, 0.f, 0.f);
#pragma unroll
        for (int j = 0; j < 3; j++) {
            int idx  = sIdx[j * MT + m];
            float s  = sScl[j * MT + m];
            const float4* row = (const float4*)(emb + (size_t)idx * DD + d0);
#pragma unroll
            for (int i = 0; i < 16; i++) {
                float4 e = row[i];
                a[i].x += s * e.x; a[i].y += s * e.y;
                a[i].z += s * e.z; a[i].w += s * e.w;
            }
        }
#pragma unroll
        for (int i = 0; i < 16; i++) {
            int d = d0 + i * 4;
            sX[(d + 0) * MT + m] = a[i].x;
            sX[(d + 1) * MT + m] = a[i].y;
            sX[(d + 2) * MT + m] = a[i].z;
            sX[(d + 3) * MT + m] = a[i].w;
        }
    }
    __syncthreads();

    // ---- view-dir branch: vh ends in sVH ----
    gemm_tile(sPE, sY,  vde_W,             vde_b,       sVH, 18,  0);
    gemm_tile(sY,  sVH, vh_W + 0 * 16384,  vh_b + 0,    sVH, DD, 1);
    gemm_tile(sVH, sY,  vh_W + 1 * 16384,  vh_b + 128,  sVH, DD, 1);
    gemm_tile(sY,  sVH, vh_W + 2 * 16384,  vh_b + 256,  sVH, DD, 1);
    // ---- hidden chain (vh modulation after block 0) ----
    gemm_tile(sX,  sY,  hid_W + 0 * 16384, hid_b + 0,   sVH, DD, 1);
    gemm_tile(sY,  sX,  hid_W + 1 * 16384, hid_b + 128, sVH, DD, 1);
    gemm_tile(sX,  sY,  hid_W + 2 * 16384, hid_b + 256, sVH, DD, 3);
    gemm_tile(sY,  sX,  hid_W + 3 * 16384, hid_b + 384, sVH, DD, 1);
    gemm_tile(sX,  sY,  hid_W + 4 * 16384, hid_b + 512, sVH, DD, 1);
    gemm_tile(sY,  sX,  hid_W + 5 * 16384, hid_b + 640, sVH, DD, 1);
    // ---- head ----
    gemm_tile(sX,  sY,  hW0, hb0, sVH, DD, 1);
    gemm_tile(sY,  sX,  hW1, hb1, sVH, DD, 1);

    // head2: 128 -> 4, no relu; write straight to gmem
    for (int i = tid; i < 512; i += NTHREADS) sW2[i] = hW2[i];
    __syncthreads();
    for (int o = tid; o < MT * 4; o += NTHREADS) {
        int m = o >> 2, c = o & 3;
        float acc = hb2[c];
#pragma unroll 8
        for (int k = 0; k < DD; k++)
            acc += sX[k * MT + m] * sW2[k * 4 + c];
        int pix = base + m;
        if (pix < n_pix) out[pix * 4 + c] = acc;
    }
}

// ---------------- launch --------------------------------------------------
extern "C" void kernel_launch(void* const* d_in, const int* in_sizes, int n_in,
                              void* d_out, int out_size)
{
    const int*   vidx  = (const int*)  d_in[0];
    const float* bary  = (const float*)d_in[1];
    const float* vdir  = (const float*)d_in[2];
    const float* emb   = (const float*)d_in[3];
    const float* vde_W = (const float*)d_in[4];
    const float* vde_b = (const float*)d_in[5];
    const float* vh_W  = (const float*)d_in[6];
    const float* vh_b  = (const float*)d_in[7];
    const float* hid_W = (const float*)d_in[8];
    const float* hid_b = (const float*)d_in[9];
    const float* hW0   = (const float*)d_in[10];
    const float* hb0   = (const float*)d_in[11];
    const float* hW1   = (const float*)d_in[12];
    const float* hb1   = (const float*)d_in[13];
    const float* hW2   = (const float*)d_in[14];
    const float* hb2   = (const float*)d_in[15];
    float* out = (float*)d_out;

    int n_pix = in_sizes[0] / 3;
    int grid  = (n_pix + MT - 1) / MT;

    // 3*16384 + 18*128 + 3*128 + 3*128 + 512 floats = 210944 B
    const int SMEM_BYTES = (3 * DD * MT + 18 * MT + 3 * MT + 3 * MT + 512) * 4;
    cudaFuncSetAttribute(rc_fused_kernel,
                         cudaFuncAttributeMaxDynamicSharedMemorySize, SMEM_BYTES);

    rc_fused_kernel<<<grid, NTHREADS, SMEM_BYTES>>>(
        vidx, bary, vdir, emb, vde_W, vde_b, vh_W, vh_b, hid_W, hid_b,
        hW0, hb0, hW1, hb1, hW2, hb2, out, n_pix);
}